// round 13
// baseline (speedup 1.0000x reference)
#include <cuda_runtime.h>
#include <cuda_bf16.h>
#include <math.h>
#include <stdint.h>

// DeepFM fused: bf16 mma.sync + cp.async weights + gather pipelined into GEMM1.
#define BB   16384
#define FF   26
#define VV   100000
#define DD   16
#define K1   416
#define HH1  256
#define HH2  128
#define EPSV 1e-5f

#define BM   128
#define TPB  512
#define NC1  13        // 416/32 k-chunks GEMM1
#define NC2  8         // 256/32 k-chunks GEMM2

#define AW   212       // A row pad (words); conflict-free frag loads
#define H1W  132
#define STW  20        // stage row words (80 B)
#define STBUF_B (256 * STW * 4)     // 20480 B

__device__ __nv_bfloat16 g_W1t[HH1 * K1];   // [n][k]
__device__ __nv_bfloat16 g_W2t[HH2 * HH1];
__device__ float g_b1f[HH1];
__device__ float g_b2f[HH2];

__global__ void deepfm_fold_kernel(
    const float* __restrict__ W1, const float* __restrict__ b1,
    const float* __restrict__ g1, const float* __restrict__ be1,
    const float* __restrict__ m1, const float* __restrict__ v1,
    const float* __restrict__ W2, const float* __restrict__ b2,
    const float* __restrict__ g2, const float* __restrict__ be2,
    const float* __restrict__ m2, const float* __restrict__ v2)
{
    int i = blockIdx.x * blockDim.x + threadIdx.x;
    const int N1 = HH1 * K1, N2 = HH2 * HH1;
    for (int idx = i; idx < N1 + N2; idx += gridDim.x * blockDim.x) {
        if (idx < N1) {
            int n = idx / K1, k = idx - n * K1;
            float sc = g1[n] * rsqrtf(v1[n] + EPSV);
            g_W1t[idx] = __float2bfloat16_rn(W1[k * HH1 + n] * sc);
        } else {
            int t2 = idx - N1;
            int n = t2 >> 8, k = t2 & 255;
            float sc = g2[n] * rsqrtf(v2[n] + EPSV);
            g_W2t[t2] = __float2bfloat16_rn(W2[k * HH2 + n] * sc);
        }
    }
    if (i < HH1) {
        float sc = g1[i] * rsqrtf(v1[i] + EPSV);
        g_b1f[i] = be1[i] + (b1[i] - m1[i]) * sc;
    }
    if (i < HH2) {
        float sc = g2[i] * rsqrtf(v2[i] + EPSV);
        g_b2f[i] = be2[i] + (b2[i] - m2[i]) * sc;
    }
}

// smem layout (H1 aliases A)
#define OFF_A    0                       // 108544
#define OFF_ST   108544                  // 61440
#define OFF_B1F  (OFF_ST + 3 * STBUF_B)  // 169984
#define OFF_B2F  (OFF_B1F + 1024)
#define OFF_W3   (OFF_B2F + 512)
#define OFF_FM   (OFF_W3 + 512)
#define OFF_LG   (OFF_FM + 512)
#define OFF_X    (OFF_LG + 1024)         // 173568
#define SMEM_BYTES (OFF_X + FF * BM * 4) // 186880

__device__ __forceinline__ void mma_bf16(float c[4], uint32_t a0, uint32_t a1,
                                         uint32_t a2, uint32_t a3,
                                         uint32_t b0, uint32_t b1)
{
    asm volatile(
        "mma.sync.aligned.m16n8k16.row.col.f32.bf16.bf16.f32 "
        "{%0,%1,%2,%3}, {%4,%5,%6,%7}, {%8,%9}, {%0,%1,%2,%3};"
        : "+f"(c[0]), "+f"(c[1]), "+f"(c[2]), "+f"(c[3])
        : "r"(a0), "r"(a1), "r"(a2), "r"(a3), "r"(b0), "r"(b1));
}

__device__ __forceinline__ void cp16(uint32_t dst_smem, const void* src) {
    asm volatile("cp.async.cg.shared.global [%0], [%1], 16;\n"
                 :: "r"(dst_smem), "l"(src));
}
__device__ __forceinline__ void cp_commit() {
    asm volatile("cp.async.commit_group;\n" ::: "memory");
}
template <int N>
__device__ __forceinline__ void cp_wait() {
    asm volatile("cp.async.wait_group %0;\n" :: "n"(N) : "memory");
}

// gather slice: features fa, fa+1; thread (m = t>>2, q = t&3) owns 16B quarters
#define GATHER_LDG(fa, ra, rb, e) do {                                        \
    int _ia = Xs[qm_m * FF + (fa)];                                           \
    int _ib = Xs[qm_m * FF + (fa) + 1];                                       \
    ra = *(const float4*)(emb2 + ((long)(fa) * VV + _ia) * DD + qm_q * 4);    \
    rb = *(const float4*)(emb2 + ((long)((fa)+1) * VV + _ib) * DD + qm_q * 4);\
    e = 0.f;                                                                  \
    if (qm_q == 0)      e = emb1[(fa) * VV + _ia];                            \
    else if (qm_q == 1) e = emb1[((fa)+1) * VV + _ib];                        \
} while (0)

#define GATHER_STS(fa, ra, rb, e) do {                                        \
    fs[0] += ra.x + rb.x; fss[0] += ra.x*ra.x + rb.x*rb.x;                    \
    fs[1] += ra.y + rb.y; fss[1] += ra.y*ra.y + rb.y*rb.y;                    \
    fs[2] += ra.z + rb.z; fss[2] += ra.z*ra.z + rb.z*rb.z;                    \
    fs[3] += ra.w + rb.w; fss[3] += ra.w*ra.w + rb.w*rb.w;                    \
    fm1 += e;                                                                 \
    __nv_bfloat162 _p; uint2 _u;                                              \
    _p = __floats2bfloat162_rn(ra.x, ra.y); _u.x = *(uint32_t*)&_p;           \
    _p = __floats2bfloat162_rn(ra.z, ra.w); _u.y = *(uint32_t*)&_p;           \
    *(uint2*)(Aw + qm_m * AW + (fa) * 8 + qm_q * 2) = _u;                     \
    _p = __floats2bfloat162_rn(rb.x, rb.y); _u.x = *(uint32_t*)&_p;           \
    _p = __floats2bfloat162_rn(rb.z, rb.w); _u.y = *(uint32_t*)&_p;           \
    *(uint2*)(Aw + qm_m * AW + ((fa)+1) * 8 + qm_q * 2) = _u;                 \
} while (0)

__global__ void __launch_bounds__(TPB, 1) deepfm_main_kernel(
    const int*   __restrict__ X,
    const float* __restrict__ emb1,
    const float* __restrict__ emb2,
    const float* __restrict__ W3,
    const float* __restrict__ b3,
    float*       __restrict__ out)
{
    extern __shared__ char smem[];
    uint32_t* Aw   = (uint32_t*)(smem + OFF_A);
    uint32_t* H1w  = Aw;                       // alias
    uint32_t* Stw  = (uint32_t*)(smem + OFF_ST);
    float* b1f_s = (float*)(smem + OFF_B1F);
    float* b2f_s = (float*)(smem + OFF_B2F);
    float* w3_s  = (float*)(smem + OFF_W3);
    float* fm_s  = (float*)(smem + OFF_FM);
    float* lg_s  = (float*)(smem + OFF_LG);
    int*   Xs    = (int*)(smem + OFF_X);
    const uint32_t st_base = (uint32_t)__cvta_generic_to_shared(Stw);

    const int t    = threadIdx.x;
    const int wid  = t >> 5;
    const int lane = t & 31;
    const int g    = lane >> 2;
    const int tig  = lane & 3;
    const int m0   = blockIdx.x * BM;
    const int qm_m = t >> 2, qm_q = t & 3;

    // -------- cp.async stage W1 chunks 0,1 --------
    #pragma unroll
    for (int ch = 0; ch < 2; ch++) {
        #pragma unroll
        for (int i = 0; i < 2; i++) {
            int idx = t + i * TPB;
            int n = idx >> 2, seg = idx & 3;
            cp16(st_base + ch * STBUF_B + n * 80 + seg * 16,
                 (const char*)g_W1t + n * (K1 * 2) + ch * 64 + seg * 16);
        }
        cp_commit();
    }

    // ---- stage small vectors ----
    if (t < HH1)                  b1f_s[t]       = g_b1f[t];
    else if (t < HH1 + HH2)       b2f_s[t - HH1] = g_b2f[t - HH1];
    else if (t < HH1 + 2 * HH2)   w3_s[t - HH1 - HH2] = W3[t - HH1 - HH2];

    // ---- X tile -> smem (coalesced) ----
    for (int i = t; i < FF * BM; i += TPB)
        Xs[i] = X[m0 * FF + i];
    __syncthreads();

    // ---- FM accumulators + gather pipeline regs ----
    float fs[4] = {0,0,0,0}, fss[4] = {0,0,0,0};
    float fm1 = 0.f;
    float4 ga, gb; float ge;

    // prologue: gather f0..3 blocking (chunks 0,1), then issue slice 0 (f4,f5)
    {
        float4 pa0, pb0, pa1, pb1; float pe0, pe1;
        GATHER_LDG(0, pa0, pb0, pe0);
        GATHER_LDG(2, pa1, pb1, pe1);
        GATHER_STS(0, pa0, pb0, pe0);
        GATHER_STS(2, pa1, pb1, pe1);
    }
    GATHER_LDG(4, ga, gb, ge);

    // =========================== GEMM1 (+pipelined gather) ===========================
    const int mb = (wid >> 1) * 16;
    const int nb1 = (wid & 1) * 128;
    float h1v[16][4];
    {
        float c[16][4];
        #pragma unroll
        for (int j = 0; j < 16; j++)
            #pragma unroll
            for (int q = 0; q < 4; q++) c[j][q] = 0.f;

        for (int ch = 0; ch < NC1; ch++) {
            if (ch < NC1 - 2) cp_wait<1>(); else cp_wait<0>();
            __syncthreads();   // chunk-ch weights ready; slice ch-2 A visible
            if (ch + 2 < NC1) {
                #pragma unroll
                for (int i = 0; i < 2; i++) {
                    int idx = t + i * TPB;
                    int n = idx >> 2, seg = idx & 3;
                    cp16(st_base + ((ch + 2) % 3) * STBUF_B + n * 80 + seg * 16,
                         (const char*)g_W1t + n * (K1 * 2) + (ch + 2) * 64 + seg * 16);
                }
                cp_commit();
            }
            const uint32_t* buf = Stw + (ch % 3) * (STBUF_B / 4);
            #pragma unroll
            for (int ksub = 0; ksub < 2; ksub++) {
                const int k0w = ch * 16 + ksub * 8;
                uint32_t a0 = Aw[(mb + g)     * AW + k0w + tig];
                uint32_t a1 = Aw[(mb + g + 8) * AW + k0w + tig];
                uint32_t a2 = Aw[(mb + g)     * AW + k0w + 4 + tig];
                uint32_t a3 = Aw[(mb + g + 8) * AW + k0w + 4 + tig];
                #pragma unroll
                for (int j = 0; j < 16; j++) {
                    int n = nb1 + j * 8 + g;
                    uint32_t b0 = buf[n * STW + ksub * 8 + tig];
                    uint32_t b1 = buf[n * STW + ksub * 8 + 4 + tig];
                    mma_bf16(c[j], a0, a1, a2, a3, b0, b1);
                }
            }
            // STS slice ch-1 (loaded last iter; = features 2ch+2,2ch+3, used chunk ch+1)
            if (ch >= 1 && ch <= 11) {
                int fa = 2 * ch + 2;
                GATHER_STS(fa, ga, gb, ge);
            }
            // issue LDG slice ch (features 2ch+4,2ch+5; STS next iter)
            if (ch <= 10) {
                int fa = 2 * ch + 4;
                GATHER_LDG(fa, ga, gb, ge);
            }
        }

        // FM finalize (regs only; fm_s separate buffer)
        {
            float part = 0.f;
            #pragma unroll
            for (int d = 0; d < 4; d++) part += fs[d] * fs[d] - fss[d];
            part = 0.5f * part + fm1;
            part += __shfl_xor_sync(0xffffffffu, part, 1);
            part += __shfl_xor_sync(0xffffffffu, part, 2);
            if (qm_q == 0) fm_s[qm_m] = part;
        }

        // stage W2 chunks 0,1 (buf (c+1)%3; bufs free: all warps past iter-12 barrier)
        #pragma unroll
        for (int c2 = 0; c2 < 2; c2++) {
            int n = t >> 2, seg = t & 3;
            cp16(st_base + ((c2 + 1) % 3) * STBUF_B + n * 80 + seg * 16,
                 (const char*)g_W2t + n * (HH1 * 2) + c2 * 64 + seg * 16);
            cp_commit();
        }

        #pragma unroll
        for (int j = 0; j < 16; j++) {
            int n = nb1 + j * 8 + tig * 2;
            h1v[j][0] = fmaxf(c[j][0] + b1f_s[n],     0.f);
            h1v[j][1] = fmaxf(c[j][1] + b1f_s[n + 1], 0.f);
            h1v[j][2] = fmaxf(c[j][2] + b1f_s[n],     0.f);
            h1v[j][3] = fmaxf(c[j][3] + b1f_s[n + 1], 0.f);
        }
    }
    __syncthreads();   // all A reads done -> safe to overwrite with H1

    #pragma unroll
    for (int j = 0; j < 16; j++) {
        int n = nb1 + j * 8 + tig * 2;
        __nv_bfloat162 plo = __floats2bfloat162_rn(h1v[j][0], h1v[j][1]);
        __nv_bfloat162 phi = __floats2bfloat162_rn(h1v[j][2], h1v[j][3]);
        H1w[(mb + g)     * H1W + (n >> 1)] = *(uint32_t*)&plo;
        H1w[(mb + g + 8) * H1W + (n >> 1)] = *(uint32_t*)&phi;
    }

    // =========================== GEMM2 + W3 ===========================
    {
        const int nb = (wid & 1) * 64;
        float c[8][4];
        #pragma unroll
        for (int j = 0; j < 8; j++)
            #pragma unroll
            for (int q = 0; q < 4; q++) c[j][q] = 0.f;

        for (int ch = 0; ch < NC2; ch++) {
            if (ch < NC2 - 2) cp_wait<1>(); else cp_wait<0>();
            __syncthreads();   // ch=0: also fences H1 stores
            if (ch + 2 < NC2) {
                int n = t >> 2, seg = t & 3;
                cp16(st_base + ((ch + 3) % 3) * STBUF_B + n * 80 + seg * 16,
                     (const char*)g_W2t + n * (HH1 * 2) + (ch + 2) * 64 + seg * 16);
                cp_commit();
            }
            const uint32_t* buf = Stw + ((ch + 1) % 3) * (STBUF_B / 4);
            #pragma unroll
            for (int ksub = 0; ksub < 2; ksub++) {
                const int k0w = ch * 16 + ksub * 8;
                uint32_t a0 = H1w[(mb + g)     * H1W + k0w + tig];
                uint32_t a1 = H1w[(mb + g + 8) * H1W + k0w + tig];
                uint32_t a2 = H1w[(mb + g)     * H1W + k0w + 4 + tig];
                uint32_t a3 = H1w[(mb + g + 8) * H1W + k0w + 4 + tig];
                #pragma unroll
                for (int j = 0; j < 8; j++) {
                    int n = nb + j * 8 + g;
                    uint32_t b0 = buf[n * STW + ksub * 8 + tig];
                    uint32_t b1 = buf[n * STW + ksub * 8 + 4 + tig];
                    mma_bf16(c[j], a0, a1, a2, a3, b0, b1);
                }
            }
        }

        float s_lo = 0.f, s_hi = 0.f;
        #pragma unroll
        for (int j = 0; j < 8; j++) {
            int n = nb + j * 8 + tig * 2;
            s_lo += fmaxf(c[j][0] + b2f_s[n],     0.f) * w3_s[n]
                  + fmaxf(c[j][1] + b2f_s[n + 1], 0.f) * w3_s[n + 1];
            s_hi += fmaxf(c[j][2] + b2f_s[n],     0.f) * w3_s[n]
                  + fmaxf(c[j][3] + b2f_s[n + 1], 0.f) * w3_s[n + 1];
        }
        s_lo += __shfl_xor_sync(0xffffffffu, s_lo, 1);
        s_lo += __shfl_xor_sync(0xffffffffu, s_lo, 2);
        s_hi += __shfl_xor_sync(0xffffffffu, s_hi, 1);
        s_hi += __shfl_xor_sync(0xffffffffu, s_hi, 2);
        if (tig == 0) {
            lg_s[(mb + g)     * 2 + (wid & 1)] = s_lo;
            lg_s[(mb + g + 8) * 2 + (wid & 1)] = s_hi;
        }
    }
    __syncthreads();

    if (t < BM) {
        float logit = lg_s[t * 2] + lg_s[t * 2 + 1] + fm_s[t] + b3[0];
        out[m0 + t] = 1.0f / (1.0f + expf(-logit));
    }
}

extern "C" void kernel_launch(void* const* d_in, const int* in_sizes, int n_in,
                              void* d_out, int out_size)
{
    const int*   X    = (const int*)  d_in[0];
    const float* emb1 = (const float*)d_in[1];
    const float* emb2 = (const float*)d_in[2];
    const float* W1   = (const float*)d_in[3];
    const float* b1   = (const float*)d_in[4];
    const float* g1   = (const float*)d_in[5];
    const float* be1  = (const float*)d_in[6];
    const float* m1   = (const float*)d_in[7];
    const float* v1   = (const float*)d_in[8];
    const float* W2   = (const float*)d_in[9];
    const float* b2   = (const float*)d_in[10];
    const float* g2   = (const float*)d_in[11];
    const float* be2  = (const float*)d_in[12];
    const float* m2   = (const float*)d_in[13];
    const float* v2   = (const float*)d_in[14];
    const float* W3   = (const float*)d_in[15];
    const float* b3   = (const float*)d_in[16];
    float* out = (float*)d_out;

    cudaFuncSetAttribute(deepfm_main_kernel,
                         cudaFuncAttributeMaxDynamicSharedMemorySize, SMEM_BYTES);

    deepfm_fold_kernel<<<272, 512>>>(W1, b1, g1, be1, m1, v1,
                                     W2, b2, g2, be2, m2, v2);
    deepfm_main_kernel<<<BB / BM, TPB, SMEM_BYTES>>>(X, emb1, emb2, W3, b3, out);
}